// round 1
// baseline (speedup 1.0000x reference)
#include <cuda_runtime.h>
#include <cuda_bf16.h>

#define BATCH   2048
#define N0      49
#define CH      768
#define MID     48
#define KSEL1   36
#define KSEL2   24
#define THREADS 256

// ---------------------------------------------------------------------------
// Preprocessed weights in device globals (no allocations allowed).
//   g_w1t[r][j*CH + c] = bf16( se{r}_w1[c, j] )   (transposed -> coalesced GEMV)
//   g_w2 [r][j*CH + c] = bf16( se{r}_w2[j, c] )   (natural layout already good)
//   g_clswt[o*CH + c]  = cls_w[c, o]              (transposed, fp32)
// ---------------------------------------------------------------------------
__device__ __nv_bfloat16 g_w1t[2][MID * CH];
__device__ __nv_bfloat16 g_w2 [2][MID * CH];
__device__ float         g_clswt[5 * CH];

__global__ void convert_weights_kernel(const float* __restrict__ w1a,
                                       const float* __restrict__ w2a,
                                       const float* __restrict__ w1b,
                                       const float* __restrict__ w2b,
                                       const float* __restrict__ clsw) {
    int i = blockIdx.x * blockDim.x + threadIdx.x;
    if (i < MID * CH) {
        int j = i / CH;
        int c = i - j * CH;
        g_w1t[0][i] = __float2bfloat16(w1a[c * MID + j]);
        g_w1t[1][i] = __float2bfloat16(w1b[c * MID + j]);
        g_w2 [0][i] = __float2bfloat16(w2a[i]);
        g_w2 [1][i] = __float2bfloat16(w2b[i]);
    }
    if (i < 5 * CH) {
        int o = i / CH;
        int c = i - o * CH;
        g_clswt[i] = clsw[c * 5 + o];
    }
}

// Shared memory layout (floats):
//   tile   [N0*CH]  raw x, gated in place per round
//   s      [CH]     column means (later: pooled)
//   gates  [CH]     per-round gates (later: normed)
//   hbuf   [MID]
//   ts     [N0]     sum-of-squares per ACTIVE-LIST POSITION
//   list   [N0] (int), nlist [N0] (int)
//   red    [20]
#define SM_FLOATS (N0*CH + CH + CH + MID + N0 + N0 + N0 + 20)
#define SM_BYTES  (SM_FLOATS * 4)

__global__ __launch_bounds__(THREADS, 1)
void coatgft_kernel(const float* __restrict__ x,
                    const float* __restrict__ b1a, const float* __restrict__ b2a,
                    const float* __restrict__ b1b, const float* __restrict__ b2b,
                    const float* __restrict__ ln_g, const float* __restrict__ ln_b,
                    const float* __restrict__ cls_b,
                    float* __restrict__ out) {
    extern __shared__ float sm[];
    float* tile  = sm;
    float* s     = tile + N0 * CH;
    float* gates = s + CH;
    float* hbuf  = gates + CH;
    float* ts    = hbuf + MID;
    int*   list  = (int*)(ts + N0);
    int*   nlist = list + N0;
    float* red   = (float*)(nlist + N0);

    const int tid  = threadIdx.x;
    const int lane = tid & 31;
    const int warp = tid >> 5;
    const int b    = blockIdx.x;

    // ---- load full 49x768 tile (float4, coalesced, DRAM read of x: once) ----
    {
        const float4* xin = (const float4*)(x + (size_t)b * N0 * CH);
        float4* t4 = (float4*)tile;
        #pragma unroll 4
        for (int i = tid; i < N0 * CH / 4; i += THREADS) t4[i] = xin[i];
    }
    if (tid < N0) list[tid] = tid;
    __syncthreads();

    int nact = N0;
    #pragma unroll 1
    for (int round = 0; round < 2; round++) {
        const __nv_bfloat16* W1t = g_w1t[round];
        const __nv_bfloat16* W2  = g_w2[round];
        const float* b1 = round ? b1b : b1a;
        const float* b2 = round ? b2b : b2a;

        // ---- s[c] = mean over active rows ----
        for (int c = tid; c < CH; c += THREADS) {
            float acc = 0.f;
            for (int i = 0; i < nact; i++) acc += tile[list[i] * CH + c];
            s[c] = acc * (1.0f / (float)nact);
        }
        __syncthreads();

        // ---- h = gelu_exact(s @ W1 + b1): warp per 6 outputs ----
        for (int j = warp; j < MID; j += 8) {
            float acc = 0.f;
            const __nv_bfloat16* wr = W1t + j * CH;
            #pragma unroll 8
            for (int c = lane; c < CH; c += 32)
                acc += s[c] * __bfloat162float(wr[c]);
            #pragma unroll
            for (int o = 16; o; o >>= 1) acc += __shfl_xor_sync(0xffffffffu, acc, o);
            if (lane == 0) {
                float z = acc + b1[j];
                hbuf[j] = 0.5f * z * (1.0f + erff(z * 0.70710678118654752f));
            }
        }
        __syncthreads();

        // ---- gates[c] = sigmoid(h @ W2 + b2) ----
        for (int c = tid; c < CH; c += THREADS) {
            float acc = b2[c];
            #pragma unroll
            for (int j = 0; j < MID; j++)
                acc += hbuf[j] * __bfloat162float(W2[j * CH + c]);
            gates[c] = 1.0f / (1.0f + expf(-acc));
        }
        __syncthreads();

        // ---- gate active rows in place; ts[i] = sum(v^2) (monotone in norm,
        //      monotone through (x-mu)/std and softmax -> same top-k) ----
        for (int i = warp; i < nact; i += 8) {
            float* row = tile + list[i] * CH;
            float acc = 0.f;
            #pragma unroll 8
            for (int c = lane; c < CH; c += 32) {
                float v = row[c] * gates[c];
                row[c] = v;
                acc += v * v;
            }
            #pragma unroll
            for (int o = 16; o; o >>= 1) acc += __shfl_xor_sync(0xffffffffu, acc, o);
            if (lane == 0) ts[i] = acc;
        }
        __syncthreads();

        // ---- selection by rank (ties -> lower position, = jax top_k) ----
        const int k = (round == 0) ? KSEL1 : KSEL2;
        if (tid < nact) {
            float mine = ts[tid];
            int rank = 0;
            for (int j = 0; j < nact; j++) {
                float tj = ts[j];
                rank += (tj > mine) || (tj == mine && j < tid);
            }
            if (rank < k) nlist[rank] = list[tid];   // rank order == top_k order
        }
        __syncthreads();
        if (tid < k) list[tid] = nlist[tid];
        nact = k;
        __syncthreads();
    }

    // ---- pooled = mean over 24 selected (gated) rows -> reuse s ----
    for (int c = tid; c < CH; c += THREADS) {
        float acc = 0.f;
        #pragma unroll
        for (int i = 0; i < KSEL2; i++) acc += tile[list[i] * CH + c];
        s[c] = acc * (1.0f / (float)KSEL2);
    }
    __syncthreads();

    // ---- LayerNorm over CH ----
    {
        float p1 = 0.f, p2 = 0.f;
        for (int c = tid; c < CH; c += THREADS) { float v = s[c]; p1 += v; p2 += v * v; }
        #pragma unroll
        for (int o = 16; o; o >>= 1) {
            p1 += __shfl_xor_sync(0xffffffffu, p1, o);
            p2 += __shfl_xor_sync(0xffffffffu, p2, o);
        }
        if (lane == 0) { red[warp] = p1; red[8 + warp] = p2; }
        __syncthreads();
        if (tid == 0) {
            float m = 0.f, m2 = 0.f;
            for (int w = 0; w < 8; w++) { m += red[w]; m2 += red[8 + w]; }
            m  *= (1.0f / CH);
            m2 *= (1.0f / CH);
            float var = m2 - m * m;
            red[16] = m;
            red[17] = rsqrtf(var + 1e-5f);
        }
        __syncthreads();
        float mu = red[16], inv = red[17];
        for (int c = tid; c < CH; c += THREADS)
            gates[c] = (s[c] - mu) * inv * ln_g[c] + ln_b[c];  // normed -> gates buf
        __syncthreads();
    }

    // ---- classifier: 5 outputs, one warp each (coalesced transposed weights) ----
    if (warp < 5) {
        float acc = 0.f;
        const float* wr = g_clswt + warp * CH;
        #pragma unroll 8
        for (int c = lane; c < CH; c += 32) acc += gates[c] * wr[c];
        #pragma unroll
        for (int o = 16; o; o >>= 1) acc += __shfl_xor_sync(0xffffffffu, acc, o);
        if (lane == 0) out[b * 5 + warp] = acc + cls_b[warp];
    }
}

extern "C" void kernel_launch(void* const* d_in, const int* in_sizes, int n_in,
                              void* d_out, int out_size) {
    // metadata order:
    // 0 x, 1 se1_w1, 2 se1_b1, 3 se1_w2, 4 se1_b2,
    // 5 se2_w1, 6 se2_b1, 7 se2_w2, 8 se2_b2,
    // 9 ln_gamma, 10 ln_beta, 11 cls_w, 12 cls_b
    const float* x    = (const float*)d_in[0];
    const float* w1a  = (const float*)d_in[1];
    const float* b1a  = (const float*)d_in[2];
    const float* w2a  = (const float*)d_in[3];
    const float* b2a  = (const float*)d_in[4];
    const float* w1b  = (const float*)d_in[5];
    const float* b1b  = (const float*)d_in[6];
    const float* w2b  = (const float*)d_in[7];
    const float* b2b  = (const float*)d_in[8];
    const float* lng  = (const float*)d_in[9];
    const float* lnb  = (const float*)d_in[10];
    const float* clsw = (const float*)d_in[11];
    const float* clsb = (const float*)d_in[12];
    float* out = (float*)d_out;

    static_assert(SM_BYTES < 232448, "smem over limit");
    cudaFuncSetAttribute(coatgft_kernel,
                         cudaFuncAttributeMaxDynamicSharedMemorySize, SM_BYTES);

    convert_weights_kernel<<<(MID * CH + 255) / 256, 256>>>(w1a, w2a, w1b, w2b, clsw);
    coatgft_kernel<<<BATCH, THREADS, SM_BYTES>>>(x, b1a, b2a, b1b, b2b,
                                                 lng, lnb, clsb, out);
}

// round 2
// speedup vs baseline: 2.0877x; 2.0877x over previous
#include <cuda_runtime.h>
#include <cuda_bf16.h>

#define BATCH   2048
#define N0      49
#define CH      768
#define MID     48
#define K1      36
#define K2      24
#define THREADS 768
#define WARPS   24
#define NF4     (N0*CH/4)   /* 9408 */

// ---------------------------------------------------------------------------
// Preprocessed weights (device globals; no runtime allocation).
//   g_w1t[r][j*CH + c] = bf16( se{r}_w1[c, j] )  transposed -> coalesced GEMV
//   g_w2 [r][j*CH + c] = bf16( se{r}_w2[j, c] )
//   g_clswt[o*CH + c]  = cls_w[c, o]             transposed, fp32
// ---------------------------------------------------------------------------
__device__ __nv_bfloat16 g_w1t[2][MID * CH];
__device__ __nv_bfloat16 g_w2 [2][MID * CH];
__device__ float         g_clswt[5 * CH];

__global__ void convert_weights_kernel(const float* __restrict__ w1a,
                                       const float* __restrict__ w2a,
                                       const float* __restrict__ w1b,
                                       const float* __restrict__ w2b,
                                       const float* __restrict__ clsw) {
    int i = blockIdx.x * blockDim.x + threadIdx.x;
    if (i < MID * CH) {
        int j = i / CH;
        int c = i - j * CH;
        g_w1t[0][i] = __float2bfloat16(w1a[c * MID + j]);
        g_w1t[1][i] = __float2bfloat16(w1b[c * MID + j]);
        g_w2 [0][i] = __float2bfloat16(w2a[i]);
        g_w2 [1][i] = __float2bfloat16(w2b[i]);
    }
    if (i < 5 * CH) {
        int o = i / CH;
        int c = i - o * CH;
        g_clswt[i] = clsw[c * 5 + o];
    }
}

// Shared memory layout (floats):
//   tile [N0*CH]  raw x (never modified after load)
//   part [4*CH]   per-group column partial sums; later reused for normed vec
//   sbuf [CH]     SE input vector s / pooled vector
//   gat  [CH]     cumulative gate product
//   hbuf [MID]
//   ts   [64]
//   list [64] int   nlist [64] int
//   red  [64]
#define SM_FLOATS (N0*CH + 4*CH + CH + CH + MID + 64 + 64 + 64 + 64)
#define SM_BYTES  (SM_FLOATS * 4)

__global__ __launch_bounds__(THREADS, 1)
void coatgft_kernel(const float* __restrict__ x,
                    const float* __restrict__ b1a, const float* __restrict__ b2a,
                    const float* __restrict__ b1b, const float* __restrict__ b2b,
                    const float* __restrict__ ln_g, const float* __restrict__ ln_b,
                    const float* __restrict__ cls_b,
                    float* __restrict__ out) {
    extern __shared__ float sm[];
    float* tile  = sm;
    float* part  = tile + N0 * CH;
    float* sbuf  = part + 4 * CH;
    float* gat   = sbuf + CH;
    float* hbuf  = gat + CH;
    float* ts    = hbuf + MID;
    int*   list  = (int*)(ts + 64);
    int*   nlist = list + 64;
    float* red   = (float*)(nlist + 64);

    const int tid  = threadIdx.x;
    const int lane = tid & 31;
    const int warp = tid >> 5;
    const int b    = blockIdx.x;

    // ================= load tile + fused round-1 column sums =================
    // linear float4 index i = tid + k*768; since 768 % 192 == 0, each thread
    // always touches float4-column (tid % 192) -> accumulate in registers.
    {
        const float4* __restrict__ xin = (const float4*)(x + (size_t)b * N0 * CH);
        float4* t4 = (float4*)tile;
        float a0 = 0.f, a1 = 0.f, a2 = 0.f, a3 = 0.f;
        #pragma unroll
        for (int k = 0; k < 13; k++) {
            int i = tid + k * THREADS;
            if (i < NF4) {
                float4 v = xin[i];
                t4[i] = v;
                a0 += v.x; a1 += v.y; a2 += v.z; a3 += v.w;
            }
        }
        int c4 = tid % 192;           // float4 column
        int g  = tid / 192;           // row-group 0..3
        float* p = part + g * CH + 4 * c4;
        p[0] = a0; p[1] = a1; p[2] = a2; p[3] = a3;
    }
    __syncthreads();

    // s[c] = colmean over 49 rows  (one thread per channel)
    {
        float cs = part[tid] + part[CH + tid] + part[2 * CH + tid] + part[3 * CH + tid];
        sbuf[tid] = cs * (1.0f / (float)N0);
    }
    __syncthreads();

    // ======================= ROUND 1 (49 -> 36) =============================
    // h = gelu(s @ W1 + b1): 2 outputs per warp
    {
        const __nv_bfloat16* W1t = g_w1t[0];
        #pragma unroll
        for (int jj = 0; jj < 2; jj++) {
            int j = warp + jj * WARPS;
            const __nv_bfloat16* wr = W1t + j * CH;
            float acc = 0.f;
            #pragma unroll
            for (int c = 0; c < CH / 32; c++)
                acc += sbuf[lane + 32 * c] * __bfloat162float(wr[lane + 32 * c]);
            #pragma unroll
            for (int o = 16; o; o >>= 1) acc += __shfl_xor_sync(0xffffffffu, acc, o);
            if (lane == 0) {
                float z = acc + b1a[j];
                hbuf[j] = 0.5f * z * (1.0f + erff(z * 0.70710678118654752f));
            }
        }
    }
    __syncthreads();

    // gates1[c] = sigmoid(h @ W2 + b2); gat = gates1
    {
        const __nv_bfloat16* W2 = g_w2[0];
        float acc = b2a[tid];
        #pragma unroll
        for (int j = 0; j < MID; j++)
            acc += hbuf[j] * __bfloat162float(W2[j * CH + tid]);
        gat[tid] = 1.0f / (1.0f + expf(-acc));
    }
    __syncthreads();

    // ts[r] = sum_c (x[r][c]*gat[c])^2   (monotone surrogate of importance)
    #pragma unroll
    for (int ii = 0; ii < 3; ii++) {
        int r = warp + ii * WARPS;
        if (r < N0) {
            const float* row = tile + r * CH;
            float acc = 0.f;
            #pragma unroll
            for (int c = 0; c < CH / 32; c++) {
                float v = row[lane + 32 * c] * gat[lane + 32 * c];
                acc += v * v;
            }
            #pragma unroll
            for (int o = 16; o; o >>= 1) acc += __shfl_xor_sync(0xffffffffu, acc, o);
            if (lane == 0) ts[r] = acc;
        }
    }
    __syncthreads();

    // rank-select top-36 (rank order == jax top_k order; ties -> lower index)
    if (tid < N0) {
        float mine = ts[tid];
        int rank = 0;
        #pragma unroll
        for (int j = 0; j < N0; j++) {
            float tj = ts[j];
            rank += (tj > mine) || (tj == mine && j < tid);
        }
        if (rank < K1) nlist[rank] = tid;
    }
    __syncthreads();
    if (tid < K1) list[tid] = nlist[tid];
    __syncthreads();

    // ======================= ROUND 2 (36 -> 24) =============================
    // s2[c] = gat[c] * (sum over 36 selected raw rows) / 36
    {
        float rs = 0.f;
        #pragma unroll
        for (int i = 0; i < K1; i++)
            rs += tile[list[i] * CH + tid];
        sbuf[tid] = rs * gat[tid] * (1.0f / (float)K1);
    }
    __syncthreads();

    {
        const __nv_bfloat16* W1t = g_w1t[1];
        #pragma unroll
        for (int jj = 0; jj < 2; jj++) {
            int j = warp + jj * WARPS;
            const __nv_bfloat16* wr = W1t + j * CH;
            float acc = 0.f;
            #pragma unroll
            for (int c = 0; c < CH / 32; c++)
                acc += sbuf[lane + 32 * c] * __bfloat162float(wr[lane + 32 * c]);
            #pragma unroll
            for (int o = 16; o; o >>= 1) acc += __shfl_xor_sync(0xffffffffu, acc, o);
            if (lane == 0) {
                float z = acc + b1b[j];
                hbuf[j] = 0.5f * z * (1.0f + erff(z * 0.70710678118654752f));
            }
        }
    }
    __syncthreads();

    // gat *= gates2
    {
        const __nv_bfloat16* W2 = g_w2[1];
        float acc = b2b[tid];
        #pragma unroll
        for (int j = 0; j < MID; j++)
            acc += hbuf[j] * __bfloat162float(W2[j * CH + tid]);
        gat[tid] *= 1.0f / (1.0f + expf(-acc));
    }
    __syncthreads();

    // ts over 36 active positions (row = list[i]), combined gate
    #pragma unroll
    for (int ii = 0; ii < 2; ii++) {
        int i = warp + ii * WARPS;
        if (i < K1) {
            const float* row = tile + list[i] * CH;
            float acc = 0.f;
            #pragma unroll
            for (int c = 0; c < CH / 32; c++) {
                float v = row[lane + 32 * c] * gat[lane + 32 * c];
                acc += v * v;
            }
            #pragma unroll
            for (int o = 16; o; o >>= 1) acc += __shfl_xor_sync(0xffffffffu, acc, o);
            if (lane == 0) ts[i] = acc;
        }
    }
    __syncthreads();

    if (tid < K1) {
        float mine = ts[tid];
        int rank = 0;
        #pragma unroll
        for (int j = 0; j < K1; j++) {
            float tj = ts[j];
            rank += (tj > mine) || (tj == mine && j < tid);
        }
        if (rank < K2) nlist[rank] = list[tid];
    }
    __syncthreads();
    if (tid < K2) list[tid] = nlist[tid];
    __syncthreads();

    // ==================== pool + LayerNorm + classifier =====================
    {
        float ps = 0.f;
        #pragma unroll
        for (int i = 0; i < K2; i++)
            ps += tile[list[i] * CH + tid];
        sbuf[tid] = ps * gat[tid] * (1.0f / (float)K2);
    }
    __syncthreads();

    {
        float v = sbuf[tid];
        float p1 = v, p2 = v * v;
        #pragma unroll
        for (int o = 16; o; o >>= 1) {
            p1 += __shfl_xor_sync(0xffffffffu, p1, o);
            p2 += __shfl_xor_sync(0xffffffffu, p2, o);
        }
        if (lane == 0) { red[warp] = p1; red[32 + warp] = p2; }
        __syncthreads();
        if (warp == 0) {
            float m  = (lane < WARPS) ? red[lane]      : 0.f;
            float m2 = (lane < WARPS) ? red[32 + lane] : 0.f;
            #pragma unroll
            for (int o = 16; o; o >>= 1) {
                m  += __shfl_xor_sync(0xffffffffu, m,  o);
                m2 += __shfl_xor_sync(0xffffffffu, m2, o);
            }
            if (lane == 0) {
                m  *= (1.0f / CH);
                m2 *= (1.0f / CH);
                red[60] = m;
                red[61] = rsqrtf(m2 - m * m + 1e-5f);
            }
        }
        __syncthreads();
        float mu = red[60], inv = red[61];
        part[tid] = (v - mu) * inv * ln_g[tid] + ln_b[tid];   // normed
    }
    __syncthreads();

    if (warp < 5) {
        const float* wr = g_clswt + warp * CH;
        float acc = 0.f;
        #pragma unroll
        for (int c = 0; c < CH / 32; c++)
            acc += part[lane + 32 * c] * wr[lane + 32 * c];
        #pragma unroll
        for (int o = 16; o; o >>= 1) acc += __shfl_xor_sync(0xffffffffu, acc, o);
        if (lane == 0) out[b * 5 + warp] = acc + cls_b[warp];
    }
}

extern "C" void kernel_launch(void* const* d_in, const int* in_sizes, int n_in,
                              void* d_out, int out_size) {
    const float* x    = (const float*)d_in[0];
    const float* w1a  = (const float*)d_in[1];
    const float* b1a  = (const float*)d_in[2];
    const float* w2a  = (const float*)d_in[3];
    const float* b2a  = (const float*)d_in[4];
    const float* w1b  = (const float*)d_in[5];
    const float* b1b  = (const float*)d_in[6];
    const float* w2b  = (const float*)d_in[7];
    const float* b2b  = (const float*)d_in[8];
    const float* lng  = (const float*)d_in[9];
    const float* lnb  = (const float*)d_in[10];
    const float* clsw = (const float*)d_in[11];
    const float* clsb = (const float*)d_in[12];
    float* out = (float*)d_out;

    static_assert(SM_BYTES < 227000, "smem over limit");
    cudaFuncSetAttribute(coatgft_kernel,
                         cudaFuncAttributeMaxDynamicSharedMemorySize, SM_BYTES);

    convert_weights_kernel<<<(MID * CH + 255) / 256, 256>>>(w1a, w2a, w1b, w2b, clsw);
    coatgft_kernel<<<BATCH, THREADS, SM_BYTES>>>(x, b1a, b2a, b1b, b2b,
                                                 lng, lnb, clsb, out);
}